// round 12
// baseline (speedup 1.0000x reference)
#include <cuda_runtime.h>
#include <cuda_bf16.h>
#include <cstdint>

// FwFM forward on GB300 — R12: warp-level HMMA Gram formulation (no tcgen05;
// harness compiles at plain sm_103, so only baseline-ISA mma.sync/ldmatrix).
//   second_order[s] = 0.5 * <W, E_s E_s^T>,  W symmetric, zero diagonal (fp32).
//   1 warp = 1 sample. E gathered to a bf16 smem tile (48 rows x 48B pitch),
//   G = E E^T via 15x mma.sync.m16n8k16 (bf16 in, fp32 accum), contracted
//   tile-by-tile with fp32 W from smem. Only E is bf16-rounded.

#define FIELDS 39
#define EDIM 16
#define BATCH 8192
#define WPITCH 41             // floats; (9r+j) mod 32 distinct over 8 rows
#define WROWS 48
#define THREADS 256
#define SPB 8                 // samples per block (= warps per block)
#define TPITCH 48             // bytes per tile row (conflict-free ldmatrix)
#define TROWS 48
#define TILE_BYTES (TROWS * TPITCH)   // 2304, multiple of 128

__device__ float g_wsym[WROWS * WPITCH];   // symmetric W, zero-padded, fp32

__device__ __forceinline__ uint32_t smem_u32(const void* p) {
    uint32_t a;
    asm("{ .reg .u64 t; cvta.to.shared.u64 t, %1; cvt.u32.u64 %0, t; }" : "=r"(a) : "l"(p));
    return a;
}

// ---- prep: build zero-padded symmetric fp32 W once per launch ----
__global__ void fwfm_prep(const float* __restrict__ fw)
{
    for (int e = threadIdx.x; e < WROWS * WPITCH; e += blockDim.x) {
        const int i = e / WPITCH, j = e - i * WPITCH;
        float w = 0.0f;
        if (i < FIELDS && j < FIELDS && i != j) {
            const int a = i < j ? i : j, b = i < j ? j : i;
            w = fw[38 * a - (a * (a - 1)) / 2 + (b - a - 1)];
        }
        g_wsym[e] = w;
    }
}

// ---- main kernel ----
__global__ __launch_bounds__(THREADS)
void fwfm_kernel(const int* __restrict__ inputs,
                 const float* __restrict__ emb,
                 const float* __restrict__ lw,
                 const float* __restrict__ bias,
                 float* __restrict__ out)
{
    __shared__ __align__(128) unsigned char etile[SPB][TILE_BYTES];
    __shared__ float wsm[WROWS * WPITCH];
    __shared__ int idx_sh[SPB * FIELDS];

    const int tid  = threadIdx.x;
    const int warp = tid >> 5;
    const int lane = tid & 31;

    // Stage indices (coalesced) and fp32 W.
    const int base = blockIdx.x * SPB * FIELDS;
    for (int k = tid; k < SPB * FIELDS; k += THREADS)
        idx_sh[k] = inputs[base + k];
    for (int e = tid; e < WROWS * WPITCH; e += THREADS)
        wsm[e] = g_wsym[e];
    __syncthreads();

    const int* ix = &idx_sh[warp * FIELDS];
    const uint32_t T = smem_u32(&etile[warp][0]);

    // Zero pad rows 39..47 (bytes 0..31 — the region ldmatrix reads).
    if (lane < 18) {
        const uint32_t a = T + (39 + (lane >> 1)) * TPITCH + (lane & 1) * 16;
        asm volatile("st.shared.v4.b32 [%0], {%1,%1,%1,%1};" :: "r"(a), "r"(0));
    }

    // Gather: two rows per iteration (lanes 0-15 row f, 16-31 row f+1),
    // convert fp32 -> bf16, store 2B into the tile.
    const int half = lane >> 4;
    const int dim  = lane & 15;
#pragma unroll
    for (int f = 0; f < FIELDS; f += 2) {
        const int r = f + half;
        if (r < FIELDS) {
            const float v = __ldg(emb + (size_t)ix[r] * EDIM + dim);
            unsigned short h;
            asm("cvt.rn.bf16.f32 %0, %1;" : "=h"(h) : "f"(v));
            asm volatile("st.shared.b16 [%0], %1;"
                         :: "r"(T + r * TPITCH + dim * 2), "h"(h));
        }
    }
    __syncwarp();

    // B fragments: 5 n-tiles of 8 rows (B = E, row.col form). x2 uses lanes 0-15.
    uint32_t b0[5], b1[5];
    {
        const uint32_t bb = T + (lane & 7) * TPITCH + ((lane >> 3) & 1) * 16;
#pragma unroll
        for (int ni = 0; ni < 5; ni++) {
            asm volatile("ldmatrix.sync.aligned.m8n8.x2.shared.b16 {%0,%1}, [%2];"
                         : "=r"(b0[ni]), "=r"(b1[ni]) : "r"(bb + ni * 8 * TPITCH));
        }
    }

    const int lrow = lane >> 2;
    const int lcol = 2 * (lane & 3);
    float acc = 0.0f;

#pragma unroll
    for (int mi = 0; mi < 3; mi++) {
        uint32_t a0, a1, a2, a3;
        const uint32_t aa = T + (16 * mi + (lane & 15)) * TPITCH + (lane >> 4) * 16;
        asm volatile("ldmatrix.sync.aligned.m8n8.x4.shared.b16 {%0,%1,%2,%3}, [%4];"
                     : "=r"(a0), "=r"(a1), "=r"(a2), "=r"(a3) : "r"(aa));
#pragma unroll
        for (int ni = 0; ni < 5; ni++) {
            float d0, d1, d2, d3;
            asm volatile(
                "mma.sync.aligned.m16n8k16.row.col.f32.bf16.bf16.f32 "
                "{%0,%1,%2,%3}, {%4,%5,%6,%7}, {%8,%9}, {%10,%11,%12,%13};"
                : "=f"(d0), "=f"(d1), "=f"(d2), "=f"(d3)
                : "r"(a0), "r"(a1), "r"(a2), "r"(a3),
                  "r"(b0[ni]), "r"(b1[ni]),
                  "f"(0.0f), "f"(0.0f), "f"(0.0f), "f"(0.0f));
            // D element (r, c): d0 (lrow, lcol), d1 (lrow, lcol+1),
            //                   d2 (lrow+8, lcol), d3 (lrow+8, lcol+1).
            const float* w0 = &wsm[(16 * mi + lrow) * WPITCH + 8 * ni + lcol];
            const float* w1 = w0 + 8 * WPITCH;
            acc = fmaf(w0[0], d0, acc);
            acc = fmaf(w0[1], d1, acc);
            acc = fmaf(w1[0], d2, acc);
            acc = fmaf(w1[1], d3, acc);
        }
    }

    // First order (fp32, exact): 39 linear-weight gathers across the warp.
    float lin = lw[ix[lane]];
    if (lane < FIELDS - 32) lin += lw[ix[32 + lane]];

    float v = 0.5f * acc + lin;
#pragma unroll
    for (int o = 16; o; o >>= 1)
        v += __shfl_xor_sync(0xffffffffu, v, o);

    if (lane == 0)
        out[blockIdx.x * SPB + warp] = v + bias[0];
}

extern "C" void kernel_launch(void* const* d_in, const int* in_sizes, int n_in,
                              void* d_out, int out_size)
{
    const int*   inputs = (const int*)d_in[0];
    const float* emb    = (const float*)d_in[1];
    const float* fw     = (const float*)d_in[2];
    const float* lw     = (const float*)d_in[3];
    const float* bias   = (const float*)d_in[4];
    float*       out    = (float*)d_out;

    fwfm_prep<<<1, 256>>>(fw);
    fwfm_kernel<<<BATCH / SPB, THREADS>>>(inputs, emb, lw, bias, out);
}

// round 13
// speedup vs baseline: 1.0135x; 1.0135x over previous
#include <cuda_runtime.h>
#include <cuda_bf16.h>
#include <cstdint>

// FwFM forward on GB300 — R13: R12 HMMA Gram + cp.async gather.
//   1 warp = 1 sample. Gather 39x64B embedding rows via 5 predicated
//   cp.async.cg (16B/lane) into fp32 smem staging -> full-row MLP with zero
//   register cost. In-place convert to the bf16 ldmatrix tile (48B pitch),
//   G = E E^T via 15x mma.sync.m16n8k16, contract with fp32 W, 0.5x.
//   Only E is bf16-rounded (rel_err ~2e-4, verified in R12).

#define FIELDS 39
#define EDIM 16
#define BATCH 8192
#define WPITCH 41             // W pitch in floats
#define WROWS 48
#define THREADS 256
#define SPB 8                 // warps (samples) per block
#define TPITCH 48             // bf16 tile pitch (bytes), conflict-free ldmatrix
#define SPITCH 80             // fp32 staging pitch (bytes), 16B-aligned rows
#define BUFB 3328             // per-warp buffer: staging 40*80=3200, rounded

__device__ float g_wsym[WROWS * WPITCH];   // symmetric W, zero-padded, fp32

__device__ __forceinline__ uint32_t smem_u32(const void* p) {
    uint32_t a;
    asm("{ .reg .u64 t; cvta.to.shared.u64 t, %1; cvt.u32.u64 %0, t; }" : "=r"(a) : "l"(p));
    return a;
}

// ---- prep: build zero-padded symmetric fp32 W once per launch ----
__global__ void fwfm_prep(const float* __restrict__ fw)
{
    for (int e = threadIdx.x; e < WROWS * WPITCH; e += blockDim.x) {
        const int i = e / WPITCH, j = e - i * WPITCH;
        float w = 0.0f;
        if (i < FIELDS && j < FIELDS && i != j) {
            const int a = i < j ? i : j, b = i < j ? j : i;
            w = fw[38 * a - (a * (a - 1)) / 2 + (b - a - 1)];
        }
        g_wsym[e] = w;
    }
}

// ---- main kernel ----
__global__ __launch_bounds__(THREADS)
void fwfm_kernel(const int* __restrict__ inputs,
                 const float* __restrict__ emb,
                 const float* __restrict__ lw,
                 const float* __restrict__ bias,
                 float* __restrict__ out)
{
    __shared__ __align__(128) unsigned char buf[SPB][BUFB];  // staging + tile (aliased)
    __shared__ float wsm[WROWS * WPITCH];
    __shared__ int idx_sh[SPB * FIELDS];

    const int tid  = threadIdx.x;
    const int warp = tid >> 5;
    const int lane = tid & 31;

    // Stage indices (coalesced) and fp32 W.
    const int base = blockIdx.x * SPB * FIELDS;
    for (int k = tid; k < SPB * FIELDS; k += THREADS)
        idx_sh[k] = inputs[base + k];
    for (int e = tid; e < WROWS * WPITCH; e += THREADS)
        wsm[e] = g_wsym[e];
    __syncthreads();

    const int* ix = &idx_sh[warp * FIELDS];
    const uint32_t T = smem_u32(&buf[warp][0]);

    // ---- async gather: 39 rows x 64B, 4 lanes/row x 16B, 5 instructions ----
    {
        const int sub = lane >> 2;          // row within group of 8
        const int seg = (lane & 3) * 4;     // float offset within row
#pragma unroll
        for (int g = 0; g < 5; g++) {
            const int r = 8 * g + sub;
            if (r < FIELDS) {
                const uint32_t dst = T + r * SPITCH + seg * 4;
                const float* src = emb + (size_t)ix[r] * EDIM + seg;
                asm volatile("cp.async.cg.shared.global [%0], [%1], 16;"
                             :: "r"(dst), "l"(src));
            }
        }
        asm volatile("cp.async.commit_group;" ::: "memory");
    }

    // First order while the gather flies (fp32, exact).
    float lin = lw[ix[lane]];
    if (lane < FIELDS - 32) lin += lw[ix[32 + lane]];

    asm volatile("cp.async.wait_group 0;" ::: "memory");
    __syncwarp();

    // ---- in-place fp32 -> bf16 conversion into the ldmatrix tile ----
    // Iter it handles rows 4it..4it+3; lane: row = 4it + (lane>>3), k = lane&7
    // reads dims (2k,2k+1) fp32, writes one bf16x2 word. Write ranges trail
    // read ranges (48r+48 <= 80(r+1)), so aliasing the buffers is safe.
    {
        const int rsub = lane >> 3;
        const int k    = lane & 7;
#pragma unroll
        for (int it = 0; it < 10; it++) {
            const int r = 4 * it + rsub;
            if (r < FIELDS) {
                float f0, f1;
                asm volatile("ld.shared.v2.f32 {%0,%1}, [%2];"
                             : "=f"(f0), "=f"(f1) : "r"(T + r * SPITCH + 8 * k));
                uint32_t h;
                asm("cvt.rn.bf16x2.f32 %0, %1, %2;" : "=r"(h) : "f"(f1), "f"(f0));
                asm volatile("st.shared.b32 [%0], %1;"
                             :: "r"(T + r * TPITCH + 4 * k), "r"(h));
            }
        }
    }
    __syncwarp();

    // Zero pad rows 39..47 (bytes 0..31 — the region ldmatrix reads).
    if (lane < 18) {
        const uint32_t a = T + (39 + (lane >> 1)) * TPITCH + (lane & 1) * 16;
        asm volatile("st.shared.v4.b32 [%0], {%1,%1,%1,%1};" :: "r"(a), "r"(0));
    }
    __syncwarp();

    // ---- B fragments: 5 n-tiles of 8 rows (B = E, row.col form) ----
    uint32_t b0[5], b1[5];
    {
        const uint32_t bb = T + (lane & 7) * TPITCH + ((lane >> 3) & 1) * 16;
#pragma unroll
        for (int ni = 0; ni < 5; ni++) {
            asm volatile("ldmatrix.sync.aligned.m8n8.x2.shared.b16 {%0,%1}, [%2];"
                         : "=r"(b0[ni]), "=r"(b1[ni]) : "r"(bb + ni * 8 * TPITCH));
        }
    }

    const int lrow = lane >> 2;
    const int lcol = 2 * (lane & 3);
    float acc = 0.0f;

#pragma unroll
    for (int mi = 0; mi < 3; mi++) {
        uint32_t a0, a1, a2, a3;
        const uint32_t aa = T + (16 * mi + (lane & 15)) * TPITCH + (lane >> 4) * 16;
        asm volatile("ldmatrix.sync.aligned.m8n8.x4.shared.b16 {%0,%1,%2,%3}, [%4];"
                     : "=r"(a0), "=r"(a1), "=r"(a2), "=r"(a3) : "r"(aa));
#pragma unroll
        for (int ni = 0; ni < 5; ni++) {
            float d0, d1, d2, d3;
            asm volatile(
                "mma.sync.aligned.m16n8k16.row.col.f32.bf16.bf16.f32 "
                "{%0,%1,%2,%3}, {%4,%5,%6,%7}, {%8,%9}, {%10,%11,%12,%13};"
                : "=f"(d0), "=f"(d1), "=f"(d2), "=f"(d3)
                : "r"(a0), "r"(a1), "r"(a2), "r"(a3),
                  "r"(b0[ni]), "r"(b1[ni]),
                  "f"(0.0f), "f"(0.0f), "f"(0.0f), "f"(0.0f));
            const float* w0 = &wsm[(16 * mi + lrow) * WPITCH + 8 * ni + lcol];
            const float* w1 = w0 + 8 * WPITCH;
            acc = fmaf(w0[0], d0, acc);
            acc = fmaf(w0[1], d1, acc);
            acc = fmaf(w1[0], d2, acc);
            acc = fmaf(w1[1], d3, acc);
        }
    }

    float v = 0.5f * acc + lin;
#pragma unroll
    for (int o = 16; o; o >>= 1)
        v += __shfl_xor_sync(0xffffffffu, v, o);

    if (lane == 0)
        out[blockIdx.x * SPB + warp] = v + bias[0];
}

extern "C" void kernel_launch(void* const* d_in, const int* in_sizes, int n_in,
                              void* d_out, int out_size)
{
    const int*   inputs = (const int*)d_in[0];
    const float* emb    = (const float*)d_in[1];
    const float* fw     = (const float*)d_in[2];
    const float* lw     = (const float*)d_in[3];
    const float* bias   = (const float*)d_in[4];
    float*       out    = (float*)d_out;

    fwfm_prep<<<1, 256>>>(fw);
    fwfm_kernel<<<BATCH / SPB, THREADS>>>(inputs, emb, lw, bias, out);
}

// round 14
// speedup vs baseline: 1.2175x; 1.2012x over previous
#include <cuda_runtime.h>
#include <cuda_bf16.h>
#include <cstdint>

// FwFM forward on GB300 — R14: HMMA Gram, zero-staging front end.
//   1 warp = 1 sample. Indices -> registers (2 coalesced LDG + shfl),
//   39 emb rows issued immediately as 10x LDG.64/lane (R4's proven request
//   shape), W staged from fw in-kernel while gathers fly. No prep kernel,
//   no pre-gather __syncthreads. Compute path identical to R12/R13:
//   G = E E^T via 15x mma.sync.m16n8k16 (bf16), contract with fp32 W, 0.5x.

#define FIELDS 39
#define EDIM 16
#define BATCH 8192
#define WPITCH 41
#define WROWS 48
#define WTOT (WROWS * WPITCH)      // 1968
#define THREADS 256
#define SPB 8                      // warps (samples) per block
#define TPITCH 48                  // bf16 tile pitch (bytes)
#define TILE_BYTES (WROWS * TPITCH)

__device__ __forceinline__ uint32_t smem_u32(const void* p) {
    uint32_t a;
    asm("{ .reg .u64 t; cvta.to.shared.u64 t, %1; cvt.u32.u64 %0, t; }" : "=r"(a) : "l"(p));
    return a;
}

__global__ __launch_bounds__(THREADS)
void fwfm_kernel(const int* __restrict__ inputs,
                 const float* __restrict__ emb,
                 const float* __restrict__ fw,
                 const float* __restrict__ lw,
                 const float* __restrict__ bias,
                 float* __restrict__ out)
{
    __shared__ __align__(128) unsigned char etile[SPB][TILE_BYTES];
    __shared__ float wsm[WTOT];

    const int tid  = threadIdx.x;
    const int warp = tid >> 5;
    const int lane = tid & 31;
    const int sample = blockIdx.x * SPB + warp;
    const uint32_t T = smem_u32(&etile[warp][0]);

    // ---- indices straight to registers (one 156B coalesced read per warp) ----
    const int* ixg = inputs + sample * FIELDS;
    const int i0 = __ldg(ixg + lane);                          // fields 0..31
    const int i1 = (lane < FIELDS - 32) ? __ldg(ixg + 32 + lane) : 0;

    // ---- issue all 39 embedding rows NOW: 10 x LDG.64 per lane ----
    // iter it: rows 4it+rsub (rsub=lane>>3); lane's k=lane&7 -> dims 2k,2k+1.
    const int rsub = lane >> 3;
    const int k    = lane & 7;
    float2 v[10];
#pragma unroll
    for (int it = 0; it < 10; it++) {
        const int r = 4 * it + rsub;                           // 0..39 (39 bogus)
        const int g = (r < 32) ? __shfl_sync(0xffffffffu, i0, r)
                               : __shfl_sync(0xffffffffu, i1, r - 32);
        v[it] = *reinterpret_cast<const float2*>(emb + (size_t)g * EDIM + 2 * k);
    }

    // ---- first order (also in flight) ----
    float lin = __ldg(lw + i0);
    if (lane < FIELDS - 32) lin += __ldg(lw + i1);

    // ---- stage symmetric fp32 W from fw while gathers fly ----
#pragma unroll
    for (int m = 0; m < 8; m++) {
        const int e = tid + THREADS * m;
        if (e < WTOT) {
            const int i = (e * 1599) >> 16;                    // e / 41
            const int j = e - i * WPITCH;
            float w = 0.0f;
            if (i < FIELDS && j < FIELDS && i != j) {
                const int a = i < j ? i : j, b = i < j ? j : i;
                w = __ldg(fw + 38 * a - (a * (a - 1)) / 2 + (b - a - 1));
            }
            wsm[e] = w;
        }
    }

    // ---- drain gathers into the bf16 tile ----
#pragma unroll
    for (int it = 0; it < 10; it++) {
        const int r = 4 * it + rsub;
        uint32_t h;
        asm("cvt.rn.bf16x2.f32 %0, %1, %2;" : "=r"(h) : "f"(v[it].y), "f"(v[it].x));
        asm volatile("st.shared.b32 [%0], %1;" :: "r"(T + r * TPITCH + 4 * k), "r"(h));
    }
    __syncwarp();

    // Zero pad rows 39..47, bytes 0..31 (covers the bogus row-39 store too).
    if (lane < 18) {
        const uint32_t a = T + (39 + (lane >> 1)) * TPITCH + (lane & 1) * 16;
        asm volatile("st.shared.v4.b32 [%0], {%1,%1,%1,%1};" :: "r"(a), "r"(0));
    }
    __syncthreads();    // tile (own warp) + wsm (all warps) ready

    // ---- B fragments: 5 n-tiles of 8 rows (B = E, row.col form) ----
    uint32_t b0[5], b1[5];
    {
        const uint32_t bb = T + (lane & 7) * TPITCH + ((lane >> 3) & 1) * 16;
#pragma unroll
        for (int ni = 0; ni < 5; ni++) {
            asm volatile("ldmatrix.sync.aligned.m8n8.x2.shared.b16 {%0,%1}, [%2];"
                         : "=r"(b0[ni]), "=r"(b1[ni]) : "r"(bb + ni * 8 * TPITCH));
        }
    }

    const int lrow = lane >> 2;
    const int lcol = 2 * (lane & 3);
    float acc = 0.0f;

#pragma unroll
    for (int mi = 0; mi < 3; mi++) {
        uint32_t a0, a1, a2, a3;
        const uint32_t aa = T + (16 * mi + (lane & 15)) * TPITCH + (lane >> 4) * 16;
        asm volatile("ldmatrix.sync.aligned.m8n8.x4.shared.b16 {%0,%1,%2,%3}, [%4];"
                     : "=r"(a0), "=r"(a1), "=r"(a2), "=r"(a3) : "r"(aa));
#pragma unroll
        for (int ni = 0; ni < 5; ni++) {
            float d0, d1, d2, d3;
            asm volatile(
                "mma.sync.aligned.m16n8k16.row.col.f32.bf16.bf16.f32 "
                "{%0,%1,%2,%3}, {%4,%5,%6,%7}, {%8,%9}, {%10,%11,%12,%13};"
                : "=f"(d0), "=f"(d1), "=f"(d2), "=f"(d3)
                : "r"(a0), "r"(a1), "r"(a2), "r"(a3),
                  "r"(b0[ni]), "r"(b1[ni]),
                  "f"(0.0f), "f"(0.0f), "f"(0.0f), "f"(0.0f));
            const float* w0 = &wsm[(16 * mi + lrow) * WPITCH + 8 * ni + lcol];
            const float* w1 = w0 + 8 * WPITCH;
            acc = fmaf(w0[0], d0, acc);
            acc = fmaf(w0[1], d1, acc);
            acc = fmaf(w1[0], d2, acc);
            acc = fmaf(w1[1], d3, acc);
        }
    }

    float r = 0.5f * acc + lin;
#pragma unroll
    for (int o = 16; o; o >>= 1)
        r += __shfl_xor_sync(0xffffffffu, r, o);

    if (lane == 0)
        out[sample] = r + bias[0];
}

extern "C" void kernel_launch(void* const* d_in, const int* in_sizes, int n_in,
                              void* d_out, int out_size)
{
    const int*   inputs = (const int*)d_in[0];
    const float* emb    = (const float*)d_in[1];
    const float* fw     = (const float*)d_in[2];
    const float* lw     = (const float*)d_in[3];
    const float* bias   = (const float*)d_in[4];
    float*       out    = (float*)d_out;

    fwfm_kernel<<<BATCH / SPB, THREADS>>>(inputs, emb, fw, lw, bias, out);
}

// round 15
// speedup vs baseline: 1.5013x; 1.2331x over previous
#include <cuda_runtime.h>
#include <cuda_bf16.h>
#include <cstdint>

// FwFM forward on GB300 — R15: upper-triangular folded W + fragment-layout
// epilogue + single-wave occupancy.
//   second_order[s] = sum_{i<j} w_ij G_ij,  G = E E^T (bf16 HMMA, fp32 accum).
//   W' upper-triangular -> only 9 of 15 m16n8k16 tiles touch i<j: skip rest.
//   W' staged per block directly into MMA fragment layout wfrag[9][32][4]
//   -> epilogue is 9x LDS.128 + 36 FMA, conflict-free.
//   __launch_bounds__(256,7): <=36 regs -> 7 blocks/SM -> one full wave.

#define FIELDS 39
#define EDIM 16
#define BATCH 8192
#define THREADS 256
#define SPB 8                      // warps (samples) per block
#define TPITCH 48                  // bf16 tile pitch (bytes)
#define TROWS 48
#define TILE_BYTES (TROWS * TPITCH)
#define NTILES 9                   // upper-triangle m16n8k16 tiles

__device__ __forceinline__ uint32_t smem_u32(const void* p) {
    uint32_t a;
    asm("{ .reg .u64 t; cvta.to.shared.u64 t, %1; cvt.u32.u64 %0, t; }" : "=r"(a) : "l"(p));
    return a;
}

__device__ __forceinline__ float wtri(const float* __restrict__ fw, int a, int b) {
    // w'(a,b): defined for a<b<FIELDS, else 0.
    if (a < b && b < FIELDS)
        return __ldg(fw + 38 * a - (a * (a - 1)) / 2 + (b - a - 1));
    return 0.0f;
}

__global__ __launch_bounds__(THREADS, 7)
void fwfm_kernel(const int* __restrict__ inputs,
                 const float* __restrict__ emb,
                 const float* __restrict__ fw,
                 const float* __restrict__ lw,
                 const float* __restrict__ bias,
                 float* __restrict__ out)
{
    __shared__ __align__(128) unsigned char etile[SPB][TILE_BYTES];
    __shared__ __align__(16) float wfrag[NTILES * 32 * 4];   // [tile][lane][4]

    const int tid  = threadIdx.x;
    const int warp = tid >> 5;
    const int lane = tid & 31;
    const int sample = blockIdx.x * SPB + warp;
    const uint32_t T = smem_u32(&etile[warp][0]);

    // ---- indices straight to registers (one coalesced read per warp) ----
    const int* ixg = inputs + sample * FIELDS;
    const int i0 = __ldg(ixg + lane);                          // fields 0..31
    const int i1 = (lane < FIELDS - 32) ? __ldg(ixg + 32 + lane) : 0;

    // ---- issue all 39 embedding rows NOW: 10 x LDG.64 per lane ----
    const int rsub = lane >> 3;
    const int k    = lane & 7;
    float2 v[10];
#pragma unroll
    for (int it = 0; it < 10; it++) {
        const int r = 4 * it + rsub;                           // 0..39 (39 bogus)
        const int g = (r < 32) ? __shfl_sync(0xffffffffu, i0, r)
                               : __shfl_sync(0xffffffffu, i1, r - 32);
        v[it] = *reinterpret_cast<const float2*>(emb + (size_t)g * EDIM + 2 * k);
    }

    // ---- first order (in flight) ----
    float lin = __ldg(lw + i0);
    if (lane < FIELDS - 32) lin += __ldg(lw + i1);

    // ---- stage W' in fragment layout while gathers fly ----
    // group g in [0,288): tile t=g>>5, lane l=g&31.
    // i = 16*mi + (l>>2), j = 8*ni + 2*(l&3); entries (i,j),(i,j+1),(i+8,j),(i+8,j+1).
#pragma unroll
    for (int m = 0; m < 2; m++) {
        const int g = tid + THREADS * m;
        if (g < NTILES * 32) {
            const int t  = g >> 5;
            const int l  = g & 31;
            const int mi = (t < 5) ? 0 : ((t < 8) ? 1 : 2);
            const int ni = (t < 5) ? t : ((t < 8) ? (t - 3) : 4);
            const int i  = 16 * mi + (l >> 2);
            const int j  = 8 * ni + 2 * (l & 3);
            const float w00 = wtri(fw, i,     j);
            const float w01 = wtri(fw, i,     j + 1);
            const float w10 = wtri(fw, i + 8, j);
            const float w11 = wtri(fw, i + 8, j + 1);
            asm volatile("st.shared.v4.f32 [%0], {%1,%2,%3,%4};"
                         :: "r"(smem_u32(wfrag) + g * 16u),
                            "f"(w00), "f"(w01), "f"(w10), "f"(w11));
        }
    }

    // ---- drain gathers into the bf16 tile ----
#pragma unroll
    for (int it = 0; it < 10; it++) {
        const int r = 4 * it + rsub;
        uint32_t h;
        asm("cvt.rn.bf16x2.f32 %0, %1, %2;" : "=r"(h) : "f"(v[it].y), "f"(v[it].x));
        asm volatile("st.shared.b32 [%0], %1;" :: "r"(T + r * TPITCH + 4 * k), "r"(h));
    }
    __syncwarp();

    // Zero pad rows 39..47, bytes 0..31 (overwrites the bogus row-39 store).
    if (lane < 18) {
        const uint32_t a = T + (39 + (lane >> 1)) * TPITCH + (lane & 1) * 16;
        asm volatile("st.shared.v4.b32 [%0], {%1,%1,%1,%1};" :: "r"(a), "r"(0));
    }
    __syncthreads();    // own-warp tile + block-wide wfrag ready

    // ---- B fragments: 5 n-tiles of 8 rows (B = E, row.col form) ----
    uint32_t b0[5], b1[5];
    {
        const uint32_t bb = T + (lane & 7) * TPITCH + ((lane >> 3) & 1) * 16;
#pragma unroll
        for (int ni = 0; ni < 5; ni++) {
            asm volatile("ldmatrix.sync.aligned.m8n8.x2.shared.b16 {%0,%1}, [%2];"
                         : "=r"(b0[ni]), "=r"(b1[ni]) : "r"(bb + ni * 8 * TPITCH));
        }
    }

    // ---- 9 upper-triangle MMA tiles + fragment-layout contraction ----
    float acc = 0.0f;
    int t = 0;
#pragma unroll
    for (int mi = 0; mi < 3; mi++) {
        uint32_t a0, a1, a2, a3;
        const uint32_t aa = T + (16 * mi + (lane & 15)) * TPITCH + (lane >> 4) * 16;
        asm volatile("ldmatrix.sync.aligned.m8n8.x4.shared.b16 {%0,%1,%2,%3}, [%4];"
                     : "=r"(a0), "=r"(a1), "=r"(a2), "=r"(a3) : "r"(aa));
#pragma unroll
        for (int ni = 2 * mi; ni < 5; ni++) {
            float d0, d1, d2, d3;
            asm volatile(
                "mma.sync.aligned.m16n8k16.row.col.f32.bf16.bf16.f32 "
                "{%0,%1,%2,%3}, {%4,%5,%6,%7}, {%8,%9}, {%10,%11,%12,%13};"
                : "=f"(d0), "=f"(d1), "=f"(d2), "=f"(d3)
                : "r"(a0), "r"(a1), "r"(a2), "r"(a3),
                  "r"(b0[ni]), "r"(b1[ni]),
                  "f"(0.0f), "f"(0.0f), "f"(0.0f), "f"(0.0f));
            float w0, w1, w2, w3;
            asm volatile("ld.shared.v4.f32 {%0,%1,%2,%3}, [%4];"
                         : "=f"(w0), "=f"(w1), "=f"(w2), "=f"(w3)
                         : "r"(smem_u32(wfrag) + (t * 32 + lane) * 16u));
            acc = fmaf(w0, d0, acc);
            acc = fmaf(w1, d1, acc);
            acc = fmaf(w2, d2, acc);
            acc = fmaf(w3, d3, acc);
            t++;
        }
    }

    float r = acc + lin;
#pragma unroll
    for (int o = 16; o; o >>= 1)
        r += __shfl_xor_sync(0xffffffffu, r, o);

    if (lane == 0)
        out[sample] = r + bias[0];
}

extern "C" void kernel_launch(void* const* d_in, const int* in_sizes, int n_in,
                              void* d_out, int out_size)
{
    const int*   inputs = (const int*)d_in[0];
    const float* emb    = (const float*)d_in[1];
    const float* fw     = (const float*)d_in[2];
    const float* lw     = (const float*)d_in[3];
    const float* bias   = (const float*)d_in[4];
    float*       out    = (float*)d_out;

    fwfm_kernel<<<BATCH / SPB, THREADS>>>(inputs, emb, fw, lw, bias, out);
}